// round 7
// baseline (speedup 1.0000x reference)
#include <cuda_runtime.h>
#include <cuda_bf16.h>
#include <math.h>
#include <stdint.h>

// Problem constants
#define BATCH 16
#define TT    4096
#define INF   256
#define OUTF  256
#define HF    512
#define MTOT  (BATCH * TT)              // 65536
#define K2    1280                      // GEMM2 K = 512 re + 512 im + 256 X
#define Y_ELEMS ((long long)MTOT * OUTF)

// ---------------------------------------------------------------------------
// Scratch (__device__ globals; no allocation APIs)
// ---------------------------------------------------------------------------
__device__ __align__(16) float          g_URe[(size_t)MTOT * HF];
__device__ __align__(16) float          g_UIm[(size_t)MTOT * HF];
__device__ __align__(16) __nv_bfloat16  g_A2hi[(size_t)MTOT * K2];
__device__ __align__(16) __nv_bfloat16  g_A2lo[(size_t)MTOT * K2];
__device__ __align__(16) __nv_bfloat16  g_Bhi[1024 * 256];
__device__ __align__(16) __nv_bfloat16  g_Blo[1024 * 256];
__device__ __align__(16) __nv_bfloat16  g_Whi[256 * K2];
__device__ __align__(16) __nv_bfloat16  g_Wlo[256 * K2];
__device__ float2 g_lam[HF];
__device__ float2 g_cvec[HF];
__device__ float  g_gamma[HF];

// ---------------------------------------------------------------------------
// PTX helpers (generic PTX only; no sm_103a-only features)
// ---------------------------------------------------------------------------
__device__ __forceinline__ uint32_t smem_u32(const void* p) {
    uint32_t a;
    asm("{ .reg .u64 t; cvta.to.shared.u64 t, %1; cvt.u32.u64 %0, t; }" : "=r"(a) : "l"(p));
    return a;
}
__device__ __forceinline__ void ldsm_x4(uint32_t& r0, uint32_t& r1, uint32_t& r2, uint32_t& r3,
                                        uint32_t addr) {
    asm volatile("ldmatrix.sync.aligned.m8n8.x4.shared.b16 {%0,%1,%2,%3}, [%4];"
                 : "=r"(r0), "=r"(r1), "=r"(r2), "=r"(r3) : "r"(addr));
}
__device__ __forceinline__ void mma16816(float* c, const uint32_t* a, uint32_t b0, uint32_t b1) {
    asm volatile(
        "mma.sync.aligned.m16n8k16.row.col.f32.bf16.bf16.f32 "
        "{%0,%1,%2,%3}, {%4,%5,%6,%7}, {%8,%9}, {%0,%1,%2,%3};"
        : "+f"(c[0]), "+f"(c[1]), "+f"(c[2]), "+f"(c[3])
        : "r"(a[0]), "r"(a[1]), "r"(a[2]), "r"(a[3]), "r"(b0), "r"(b1));
}
__device__ __forceinline__ void cp_async16(uint32_t sdst, const void* gsrc) {
    asm volatile("cp.async.cg.shared.global [%0], [%1], 16;"
                 :: "r"(sdst), "l"(__cvta_generic_to_global(gsrc)) : "memory");
}
#define CP_COMMIT()  asm volatile("cp.async.commit_group;" ::: "memory")
#define CP_WAIT(n)   asm volatile("cp.async.wait_group %0;" :: "n"(n) : "memory")

// ---------------------------------------------------------------------------
// SMEM: 2 stages x 4 tiles of 128 rows x 32 bf16, row stride 80 B
// ---------------------------------------------------------------------------
#define TSTR   80
#define TILE_B (128 * TSTR)             // 10240
#define S_A_HI 0
#define S_A_LO (TILE_B)
#define S_B_HI (2 * TILE_B)
#define S_B_LO (3 * TILE_B)
#define STAGE_B (4 * TILE_B)            // 40960
#define SMEM_BYTES (2 * STAGE_B)        // 81920

__device__ __forceinline__ void ld_tile_async(uint32_t sbase, const __nv_bfloat16* __restrict__ g,
                                              int ld, int tid) {
#pragma unroll
    for (int it = 0; it < 2; it++) {
        int u = tid + it * 256;
        int r = u >> 2, j = u & 3;
        cp_async16(sbase + r * TSTR + j * 16, g + (size_t)r * ld + j * 8);
    }
}

__device__ __forceinline__ void ld_stage(uint32_t sb,
                                         const __nv_bfloat16* Ahi, const __nv_bfloat16* Alo, int lda,
                                         const __nv_bfloat16* Bhi, const __nv_bfloat16* Blo, int ldb,
                                         int kc, int tid) {
    ld_tile_async(sb + S_A_HI, Ahi + kc * 32, lda, tid);
    ld_tile_async(sb + S_A_LO, Alo + kc * 32, lda, tid);
    ld_tile_async(sb + S_B_HI, Bhi + kc * 32, ldb, tid);
    ld_tile_async(sb + S_B_LO, Blo + kc * 32, ldb, tid);
}

// Compute one BK=32 chunk. Phase-ordered for max RAW distance between
// same-accumulator HMMAs (16 independent acc chains per phase).
__device__ __forceinline__ void compute_chunk(float acc[2][8][4], uint32_t sb,
                                              int lane, int wm, int wn) {
    const int a_row = wm * 32 + (lane & 15);
    const uint32_t a_coff = (uint32_t)((lane >> 4) << 4);
    const int b_rowl = (lane & 7) + ((lane >> 4) << 3);
    const uint32_t b_coff = (uint32_t)(((lane >> 3) & 1) << 4);

#pragma unroll
    for (int k16 = 0; k16 < 2; k16++) {
        const uint32_t koff = (uint32_t)(k16 * 32);
        uint32_t ah[2][4], al[2][4], bx[4][4];

        // A-hi + B-hi fragments
        ldsm_x4(ah[0][0], ah[0][1], ah[0][2], ah[0][3],
                sb + S_A_HI + (uint32_t)a_row * TSTR + koff + a_coff);
        ldsm_x4(ah[1][0], ah[1][1], ah[1][2], ah[1][3],
                sb + S_A_HI + (uint32_t)(a_row + 16) * TSTR + koff + a_coff);
#pragma unroll
        for (int ng = 0; ng < 4; ng++)
            ldsm_x4(bx[ng][0], bx[ng][1], bx[ng][2], bx[ng][3],
                    sb + S_B_HI + (uint32_t)(wn * 64 + ng * 16 + b_rowl) * TSTR + koff + b_coff);

        // phase 1: hi*hi — 16 mmas, all 16 accumulators distinct
#pragma unroll
        for (int ng = 0; ng < 4; ng++) {
            mma16816(acc[0][2 * ng],     ah[0], bx[ng][0], bx[ng][1]);
            mma16816(acc[0][2 * ng + 1], ah[0], bx[ng][2], bx[ng][3]);
            mma16816(acc[1][2 * ng],     ah[1], bx[ng][0], bx[ng][1]);
            mma16816(acc[1][2 * ng + 1], ah[1], bx[ng][2], bx[ng][3]);
        }

        // A-lo fragments
        ldsm_x4(al[0][0], al[0][1], al[0][2], al[0][3],
                sb + S_A_LO + (uint32_t)a_row * TSTR + koff + a_coff);
        ldsm_x4(al[1][0], al[1][1], al[1][2], al[1][3],
                sb + S_A_LO + (uint32_t)(a_row + 16) * TSTR + koff + a_coff);

        // phase 2: lo*hi — same accs, RAW distance 16
#pragma unroll
        for (int ng = 0; ng < 4; ng++) {
            mma16816(acc[0][2 * ng],     al[0], bx[ng][0], bx[ng][1]);
            mma16816(acc[0][2 * ng + 1], al[0], bx[ng][2], bx[ng][3]);
            mma16816(acc[1][2 * ng],     al[1], bx[ng][0], bx[ng][1]);
            mma16816(acc[1][2 * ng + 1], al[1], bx[ng][2], bx[ng][3]);
        }

        // phase 3: hi*lo — B-lo reloaded into dead B-hi regs, two halves
#pragma unroll
        for (int half = 0; half < 2; half++) {
#pragma unroll
            for (int q = 0; q < 2; q++) {
                int ng = half * 2 + q;
                ldsm_x4(bx[ng][0], bx[ng][1], bx[ng][2], bx[ng][3],
                        sb + S_B_LO + (uint32_t)(wn * 64 + ng * 16 + b_rowl) * TSTR + koff + b_coff);
            }
#pragma unroll
            for (int q = 0; q < 2; q++) {
                int ng = half * 2 + q;
                mma16816(acc[0][2 * ng],     ah[0], bx[ng][0], bx[ng][1]);
                mma16816(acc[0][2 * ng + 1], ah[0], bx[ng][2], bx[ng][3]);
                mma16816(acc[1][2 * ng],     ah[1], bx[ng][0], bx[ng][1]);
                mma16816(acc[1][2 * ng + 1], ah[1], bx[ng][2], bx[ng][3]);
            }
        }
    }
}

// Double-buffered GEMM core.
__device__ __forceinline__ void gemm_core(
    float acc[2][8][4],
    const __nv_bfloat16* __restrict__ Ahi, const __nv_bfloat16* __restrict__ Alo, int lda,
    const __nv_bfloat16* __restrict__ Bhi, const __nv_bfloat16* __restrict__ Blo, int ldb,
    int kChunks, uint32_t sb, int tid) {

    const int lane = tid & 31;
    const int warp = tid >> 5;
    const int wm = warp & 3, wn = warp >> 2;

    ld_stage(sb, Ahi, Alo, lda, Bhi, Blo, ldb, 0, tid);
    CP_COMMIT();

    for (int kc = 0; kc < kChunks; kc++) {
        if (kc + 1 < kChunks) {
            ld_stage(sb + ((kc + 1) & 1) * STAGE_B, Ahi, Alo, lda, Bhi, Blo, ldb, kc + 1, tid);
            CP_COMMIT();
            CP_WAIT(1);
        } else {
            CP_WAIT(0);
        }
        __syncthreads();
        compute_chunk(acc, sb + (kc & 1) * STAGE_B, lane, wm, wn);
        __syncthreads();
    }
}

// ---------------------------------------------------------------------------
// Prep kernels
// ---------------------------------------------------------------------------
__global__ void prep_kernel(const float* __restrict__ nu_log,
                            const float* __restrict__ theta_log,
                            const float* __restrict__ bh_re,
                            const float* __restrict__ bh_im) {
    int h = threadIdx.x;
    if (h >= HF) return;
    float en = expf(nu_log[h]);
    float et = expf(theta_log[h]);
    float mag = expf(-en);
    float s, c;
    sincosf(et, &s, &c);
    g_lam[h] = make_float2(mag * c, mag * s);
    float gam = sqrtf(fmaxf(0.0f, 1.0f - mag * mag));
    g_gamma[h] = gam;
    g_cvec[h] = make_float2((gam + 1.0f) * bh_re[h], (gam + 1.0f) * bh_im[h]);
}

__device__ __forceinline__ void split_bf16(float x, __nv_bfloat16& h, __nv_bfloat16& l) {
    h = __float2bfloat16(x);
    l = __float2bfloat16(x - __bfloat162float(h));
}

__global__ void wprep_kernel(const float* __restrict__ Bre, const float* __restrict__ Bim,
                             const float* __restrict__ Cre, const float* __restrict__ Cim,
                             const float* __restrict__ D) {
    int n = blockIdx.x * blockDim.x + threadIdx.x;
    if (n < 1024 * 256) {
        int r = n >> 8, i = n & 255;
        float v = (r < 512) ? Bre[r * 256 + i] : Bim[(r - 512) * 256 + i];
        __nv_bfloat16 h, l; split_bf16(v, h, l);
        g_Bhi[n] = h; g_Blo[n] = l;
    } else {
        int n2 = n - 1024 * 256;
        if (n2 < 256 * K2) {
            int o = n2 / K2, k = n2 % K2;
            float v;
            if (k < 512)       v = Cre[o * 512 + k];
            else if (k < 1024) v = -Cim[o * 512 + (k - 512)];
            else               v = D[o * 256 + (k - 1024)];
            __nv_bfloat16 h, l; split_bf16(v, h, l);
            g_Whi[n2] = h; g_Wlo[n2] = l;
        }
    }
}

__global__ void convx_kernel(const float* __restrict__ X) {
    long long g4 = (long long)blockIdx.x * blockDim.x + threadIdx.x;
    if (g4 >= (long long)MTOT * INF / 4) return;
    int m = (int)(g4 >> 6), i = (int)(g4 & 63) * 4;
    float4 v = *reinterpret_cast<const float4*>(X + (size_t)m * INF + i);
    __nv_bfloat16 h0, l0, h1, l1, h2, l2, h3, l3;
    split_bf16(v.x, h0, l0); split_bf16(v.y, h1, l1);
    split_bf16(v.z, h2, l2); split_bf16(v.w, h3, l3);
    size_t idx = (size_t)m * K2 + 1024 + i;
    *reinterpret_cast<__nv_bfloat162*>(g_A2hi + idx)     = __nv_bfloat162(h0, h1);
    *reinterpret_cast<__nv_bfloat162*>(g_A2hi + idx + 2) = __nv_bfloat162(h2, h3);
    *reinterpret_cast<__nv_bfloat162*>(g_A2lo + idx)     = __nv_bfloat162(l0, l1);
    *reinterpret_cast<__nv_bfloat162*>(g_A2lo + idx + 2) = __nv_bfloat162(l2, l3);
}

// ---------------------------------------------------------------------------
// GEMM1: U[m, 0..1023] = gamma * (Xsplit . BcatT), fp32 planar out (URe|UIm)
// ---------------------------------------------------------------------------
__global__ __launch_bounds__(256, 2) void gemm1_kernel() {
    extern __shared__ char smem[];
    uint32_t sb = smem_u32(smem);
    const int tid = threadIdx.x;
    const int lane = tid & 31;
    const int warp = tid >> 5;
    const int wm = warp & 3, wn = warp >> 2;
    const int mBase = blockIdx.y * 128;
    const int colBase = blockIdx.x * 128;

    float acc[2][8][4];
#pragma unroll
    for (int a = 0; a < 2; a++)
#pragma unroll
        for (int b = 0; b < 8; b++)
#pragma unroll
            for (int c = 0; c < 4; c++) acc[a][b][c] = 0.f;

    gemm_core(acc,
              g_A2hi + (size_t)mBase * K2 + 1024,
              g_A2lo + (size_t)mBase * K2 + 1024, K2,
              g_Bhi + (size_t)colBase * 256,
              g_Blo + (size_t)colBase * 256, 256,
              8, sb, tid);

    float* dst = (colBase < 512) ? g_URe : g_UIm;
#pragma unroll
    for (int nt = 0; nt < 8; nt++) {
        int col = colBase + wn * 64 + nt * 8 + (lane & 3) * 2;
        int h = col & 511;
        float g0 = g_gamma[h], g1 = g_gamma[h + 1];
#pragma unroll
        for (int mt = 0; mt < 2; mt++) {
            float* c = acc[mt][nt];
            int m0 = mBase + wm * 32 + mt * 16 + (lane >> 2);
            *reinterpret_cast<float2*>(&dst[(size_t)m0 * 512 + h]) =
                make_float2(c[0] * g0, c[1] * g1);
            *reinterpret_cast<float2*>(&dst[(size_t)(m0 + 8) * 512 + h]) =
                make_float2(c[2] * g0, c[3] * g1);
        }
    }
}

// ---------------------------------------------------------------------------
// Scan: chunked-parallel, 16 chunks of 256 (+64 warmup; lambda^64 ~ 1.6e-28).
// ---------------------------------------------------------------------------
#define SCH   256
#define SWARM 64
__global__ __launch_bounds__(256) void scan_kernel(float* __restrict__ out_hN) {
    int g = blockIdx.x * blockDim.x + threadIdx.x;
    int h = g & 511;
    int ch = (g >> 9) & 15;
    int b = g >> 13;
    const float2 lam = g_lam[h];
    const float2 cv = g_cvec[h];
    float hr = 0.f, hi = 0.f;
    const int t0 = ch * SCH;
    const int tw = (ch == 0) ? 0 : t0 - SWARM;
    size_t ub = ((size_t)b * TT + tw) * HF + h;
    for (int t = tw; t < t0; t++) {
        float vr = g_URe[ub] + cv.x;
        float vi = g_UIm[ub] + cv.y;
        float nr = fmaf(lam.x, hr, fmaf(-lam.y, hi, vr));
        float ni = fmaf(lam.x, hi, fmaf(lam.y, hr, vi));
        hr = nr; hi = ni; ub += HF;
    }
    size_t arow = ((size_t)b * TT + t0) * K2;
    for (int t = 0; t < SCH; t++) {
        float vr = g_URe[ub] + cv.x;
        float vi = g_UIm[ub] + cv.y;
        float nr = fmaf(lam.x, hr, fmaf(-lam.y, hi, vr));
        float ni = fmaf(lam.x, hi, fmaf(lam.y, hr, vi));
        hr = nr; hi = ni; ub += HF;
        __nv_bfloat16 rh, rl, ih, il;
        split_bf16(hr, rh, rl);
        split_bf16(hi, ih, il);
        g_A2hi[arow + h] = rh;       g_A2lo[arow + h] = rl;
        g_A2hi[arow + 512 + h] = ih; g_A2lo[arow + 512 + h] = il;
        arow += K2;
    }
    if (ch == 15) {
        int g2 = b * 512 + h;
        out_hN[g2] = hr;
        out_hN[BATCH * HF + g2] = hi;
    }
}

// ---------------------------------------------------------------------------
// GEMM2: Y[m, 256] = A2split . WcatT + bias   (K = 1280)
// ---------------------------------------------------------------------------
__global__ __launch_bounds__(256, 2) void gemm2_kernel(const float* __restrict__ bias,
                                                       float* __restrict__ Y) {
    extern __shared__ char smem[];
    uint32_t sb = smem_u32(smem);
    const int tid = threadIdx.x;
    const int lane = tid & 31;
    const int warp = tid >> 5;
    const int wm = warp & 3, wn = warp >> 2;
    const int mBase = blockIdx.y * 128;
    const int colBase = blockIdx.x * 128;

    float acc[2][8][4];
#pragma unroll
    for (int a = 0; a < 2; a++)
#pragma unroll
        for (int b = 0; b < 8; b++)
#pragma unroll
            for (int c = 0; c < 4; c++) acc[a][b][c] = 0.f;

    gemm_core(acc,
              g_A2hi + (size_t)mBase * K2,
              g_A2lo + (size_t)mBase * K2, K2,
              g_Whi + (size_t)colBase * K2,
              g_Wlo + (size_t)colBase * K2, K2,
              40, sb, tid);

#pragma unroll
    for (int nt = 0; nt < 8; nt++) {
        int col = colBase + wn * 64 + nt * 8 + (lane & 3) * 2;
        float b0 = bias[col], b1 = bias[col + 1];
#pragma unroll
        for (int mt = 0; mt < 2; mt++) {
            float* c = acc[mt][nt];
            int m0 = mBase + wm * 32 + mt * 16 + (lane >> 2);
            *reinterpret_cast<float2*>(&Y[(size_t)m0 * OUTF + col]) =
                make_float2(c[0] + b0, c[1] + b1);
            *reinterpret_cast<float2*>(&Y[(size_t)(m0 + 8) * OUTF + col]) =
                make_float2(c[2] + b0, c[3] + b1);
        }
    }
}

// ---------------------------------------------------------------------------
// Launch
// ---------------------------------------------------------------------------
extern "C" void kernel_launch(void* const* d_in, const int* in_sizes, int n_in,
                              void* d_out, int out_size) {
    const float* X      = (const float*)d_in[0];
    const float* nu_log = (const float*)d_in[1];
    const float* th_log = (const float*)d_in[2];
    const float* Bre    = (const float*)d_in[3];
    const float* Bim    = (const float*)d_in[4];
    const float* Cre    = (const float*)d_in[5];
    const float* Cim    = (const float*)d_in[6];
    const float* D      = (const float*)d_in[7];
    const float* bh_re  = (const float*)d_in[8];
    const float* bh_im  = (const float*)d_in[9];
    const float* bias   = (const float*)d_in[10];

    float* Y = (float*)d_out;
    float* out_hN = Y + Y_ELEMS;

    static int smem_set = 0;
    if (!smem_set) {
        cudaFuncSetAttribute(gemm1_kernel, cudaFuncAttributeMaxDynamicSharedMemorySize, SMEM_BYTES);
        cudaFuncSetAttribute(gemm2_kernel, cudaFuncAttributeMaxDynamicSharedMemorySize, SMEM_BYTES);
        smem_set = 1;
    }

    prep_kernel<<<1, HF>>>(nu_log, th_log, bh_re, bh_im);

    int wtot = 1024 * 256 + 256 * K2;
    wprep_kernel<<<(wtot + 255) / 256, 256>>>(Bre, Bim, Cre, Cim, D);

    convx_kernel<<<(MTOT * INF / 4 + 255) / 256, 256>>>(X);

    dim3 g1(8, MTOT / 128);
    gemm1_kernel<<<g1, 256, SMEM_BYTES>>>();

    scan_kernel<<<(BATCH * 16 * HF) / 256, 256>>>(out_hN);

    dim3 g2(2, MTOT / 128);
    gemm2_kernel<<<g2, 256, SMEM_BYTES>>>(bias, Y);
}

// round 8
// speedup vs baseline: 1.2692x; 1.2692x over previous
#include <cuda_runtime.h>
#include <cuda_fp16.h>
#include <math.h>
#include <stdint.h>

// Problem constants
#define BATCH 16
#define TT    4096
#define INF   256
#define OUTF  256
#define HF    512
#define MTOT  (BATCH * TT)              // 65536
#define K2    1280                      // GEMM2 K = 512 re + 512 im + 256 X
#define Y_ELEMS ((long long)MTOT * OUTF)

// ---------------------------------------------------------------------------
// Scratch (__device__ globals; no allocation APIs)
// ---------------------------------------------------------------------------
__device__ __align__(16) float   g_URe[(size_t)MTOT * HF];
__device__ __align__(16) float   g_UIm[(size_t)MTOT * HF];
__device__ __align__(16) __half  g_A2[(size_t)MTOT * K2];     // single fp16 activations
__device__ __align__(16) __half  g_Bhi[1024 * 256];
__device__ __align__(16) __half  g_Blo[1024 * 256];
__device__ __align__(16) __half  g_Whi[256 * K2];
__device__ __align__(16) __half  g_Wlo[256 * K2];
__device__ float2 g_lam[HF];
__device__ float2 g_cvec[HF];
__device__ float  g_gamma[HF];

// ---------------------------------------------------------------------------
// PTX helpers (generic PTX only; no sm_103a-only features)
// ---------------------------------------------------------------------------
__device__ __forceinline__ uint32_t smem_u32(const void* p) {
    uint32_t a;
    asm("{ .reg .u64 t; cvta.to.shared.u64 t, %1; cvt.u32.u64 %0, t; }" : "=r"(a) : "l"(p));
    return a;
}
__device__ __forceinline__ void ldsm_x4(uint32_t& r0, uint32_t& r1, uint32_t& r2, uint32_t& r3,
                                        uint32_t addr) {
    asm volatile("ldmatrix.sync.aligned.m8n8.x4.shared.b16 {%0,%1,%2,%3}, [%4];"
                 : "=r"(r0), "=r"(r1), "=r"(r2), "=r"(r3) : "r"(addr));
}
__device__ __forceinline__ void mma16816(float* c, const uint32_t* a, uint32_t b0, uint32_t b1) {
    asm volatile(
        "mma.sync.aligned.m16n8k16.row.col.f32.f16.f16.f32 "
        "{%0,%1,%2,%3}, {%4,%5,%6,%7}, {%8,%9}, {%0,%1,%2,%3};"
        : "+f"(c[0]), "+f"(c[1]), "+f"(c[2]), "+f"(c[3])
        : "r"(a[0]), "r"(a[1]), "r"(a[2]), "r"(a[3]), "r"(b0), "r"(b1));
}
__device__ __forceinline__ void cp_async16(uint32_t sdst, const void* gsrc) {
    asm volatile("cp.async.cg.shared.global [%0], [%1], 16;"
                 :: "r"(sdst), "l"(__cvta_generic_to_global(gsrc)) : "memory");
}
#define CP_COMMIT()  asm volatile("cp.async.commit_group;" ::: "memory")
#define CP_WAIT(n)   asm volatile("cp.async.wait_group %0;" :: "n"(n) : "memory")

// ---------------------------------------------------------------------------
// SMEM: 2 stages x 3 tiles of 128 rows x 32 fp16, row stride 80 B
// (80 = 5*16: cp.async-16 aligned; ldmatrix conflict-free)
// ---------------------------------------------------------------------------
#define TSTR   80
#define TILE_B (128 * TSTR)             // 10240
#define S_A    0
#define S_B_HI (TILE_B)
#define S_B_LO (2 * TILE_B)
#define STAGE_B (3 * TILE_B)            // 30720
#define SMEM_BYTES (2 * STAGE_B)        // 61440

__device__ __forceinline__ void ld_tile_async(uint32_t sbase, const __half* __restrict__ g,
                                              int ld, int tid) {
#pragma unroll
    for (int it = 0; it < 2; it++) {
        int u = tid + it * 256;
        int r = u >> 2, j = u & 3;
        cp_async16(sbase + r * TSTR + j * 16, g + (size_t)r * ld + j * 8);
    }
}

__device__ __forceinline__ void ld_stage(uint32_t sb,
                                         const __half* A, int lda,
                                         const __half* Bhi, const __half* Blo, int ldb,
                                         int kc, int tid) {
    ld_tile_async(sb + S_A,    A   + kc * 32, lda, tid);
    ld_tile_async(sb + S_B_HI, Bhi + kc * 32, ldb, tid);
    ld_tile_async(sb + S_B_LO, Blo + kc * 32, ldb, tid);
}

// Compute one BK=32 chunk: acc += A·B_hi + A·B_lo (2-pass fp16 weight-split).
__device__ __forceinline__ void compute_chunk(float acc[2][8][4], uint32_t sb,
                                              int lane, int wm, int wn) {
    const int a_row = wm * 32 + (lane & 15);
    const uint32_t a_coff = (uint32_t)((lane >> 4) << 4);
    const int b_rowl = (lane & 7) + ((lane >> 4) << 3);
    const uint32_t b_coff = (uint32_t)(((lane >> 3) & 1) << 4);

#pragma unroll
    for (int k16 = 0; k16 < 2; k16++) {
        const uint32_t koff = (uint32_t)(k16 * 32);
        uint32_t ah[2][4], bx[4][4];

        ldsm_x4(ah[0][0], ah[0][1], ah[0][2], ah[0][3],
                sb + S_A + (uint32_t)a_row * TSTR + koff + a_coff);
        ldsm_x4(ah[1][0], ah[1][1], ah[1][2], ah[1][3],
                sb + S_A + (uint32_t)(a_row + 16) * TSTR + koff + a_coff);
#pragma unroll
        for (int ng = 0; ng < 4; ng++)
            ldsm_x4(bx[ng][0], bx[ng][1], bx[ng][2], bx[ng][3],
                    sb + S_B_HI + (uint32_t)(wn * 64 + ng * 16 + b_rowl) * TSTR + koff + b_coff);

        // pass 1: A * B_hi (16 mmas, 16 distinct accumulators)
#pragma unroll
        for (int ng = 0; ng < 4; ng++) {
            mma16816(acc[0][2 * ng],     ah[0], bx[ng][0], bx[ng][1]);
            mma16816(acc[0][2 * ng + 1], ah[0], bx[ng][2], bx[ng][3]);
            mma16816(acc[1][2 * ng],     ah[1], bx[ng][0], bx[ng][1]);
            mma16816(acc[1][2 * ng + 1], ah[1], bx[ng][2], bx[ng][3]);
        }

        // pass 2: A * B_lo (reload into dead B regs)
#pragma unroll
        for (int ng = 0; ng < 4; ng++)
            ldsm_x4(bx[ng][0], bx[ng][1], bx[ng][2], bx[ng][3],
                    sb + S_B_LO + (uint32_t)(wn * 64 + ng * 16 + b_rowl) * TSTR + koff + b_coff);
#pragma unroll
        for (int ng = 0; ng < 4; ng++) {
            mma16816(acc[0][2 * ng],     ah[0], bx[ng][0], bx[ng][1]);
            mma16816(acc[0][2 * ng + 1], ah[0], bx[ng][2], bx[ng][3]);
            mma16816(acc[1][2 * ng],     ah[1], bx[ng][0], bx[ng][1]);
            mma16816(acc[1][2 * ng + 1], ah[1], bx[ng][2], bx[ng][3]);
        }
    }
}

// Double-buffered GEMM core.
__device__ __forceinline__ void gemm_core(
    float acc[2][8][4],
    const __half* __restrict__ A, int lda,
    const __half* __restrict__ Bhi, const __half* __restrict__ Blo, int ldb,
    int kChunks, uint32_t sb, int tid) {

    const int lane = tid & 31;
    const int warp = tid >> 5;
    const int wm = warp & 3, wn = warp >> 2;

    ld_stage(sb, A, lda, Bhi, Blo, ldb, 0, tid);
    CP_COMMIT();

    for (int kc = 0; kc < kChunks; kc++) {
        if (kc + 1 < kChunks) {
            ld_stage(sb + ((kc + 1) & 1) * STAGE_B, A, lda, Bhi, Blo, ldb, kc + 1, tid);
            CP_COMMIT();
            CP_WAIT(1);
        } else {
            CP_WAIT(0);
        }
        __syncthreads();
        compute_chunk(acc, sb + (kc & 1) * STAGE_B, lane, wm, wn);
        __syncthreads();
    }
}

// ---------------------------------------------------------------------------
// Prep kernels
// ---------------------------------------------------------------------------
__global__ void prep_kernel(const float* __restrict__ nu_log,
                            const float* __restrict__ theta_log,
                            const float* __restrict__ bh_re,
                            const float* __restrict__ bh_im) {
    int h = threadIdx.x;
    if (h >= HF) return;
    float en = expf(nu_log[h]);
    float et = expf(theta_log[h]);
    float mag = expf(-en);
    float s, c;
    sincosf(et, &s, &c);
    g_lam[h] = make_float2(mag * c, mag * s);
    float gam = sqrtf(fmaxf(0.0f, 1.0f - mag * mag));
    g_gamma[h] = gam;
    g_cvec[h] = make_float2((gam + 1.0f) * bh_re[h], (gam + 1.0f) * bh_im[h]);
}

__device__ __forceinline__ void split_f16(float x, __half& h, __half& l) {
    h = __float2half(x);
    l = __float2half(x - __half2float(h));
}

// Weights: Bcat = [Bre; Bim] (1024x256), Wcat = [Cre | -Cim | D] (256x1280)
__global__ void wprep_kernel(const float* __restrict__ Bre, const float* __restrict__ Bim,
                             const float* __restrict__ Cre, const float* __restrict__ Cim,
                             const float* __restrict__ D) {
    int n = blockIdx.x * blockDim.x + threadIdx.x;
    if (n < 1024 * 256) {
        int r = n >> 8, i = n & 255;
        float v = (r < 512) ? Bre[r * 256 + i] : Bim[(r - 512) * 256 + i];
        __half h, l; split_f16(v, h, l);
        g_Bhi[n] = h; g_Blo[n] = l;
    } else {
        int n2 = n - 1024 * 256;
        if (n2 < 256 * K2) {
            int o = n2 / K2, k = n2 % K2;
            float v;
            if (k < 512)       v = Cre[o * 512 + k];
            else if (k < 1024) v = -Cim[o * 512 + (k - 512)];
            else               v = D[o * 256 + (k - 1024)];
            __half h, l; split_f16(v, h, l);
            g_Whi[n2] = h; g_Wlo[n2] = l;
        }
    }
}

// X -> fp16 into A2 cols [1024..1279]
__global__ void convx_kernel(const float* __restrict__ X) {
    long long g4 = (long long)blockIdx.x * blockDim.x + threadIdx.x;
    if (g4 >= (long long)MTOT * INF / 4) return;
    int m = (int)(g4 >> 6), i = (int)(g4 & 63) * 4;
    float4 v = *reinterpret_cast<const float4*>(X + (size_t)m * INF + i);
    size_t idx = (size_t)m * K2 + 1024 + i;
    *reinterpret_cast<__half2*>(g_A2 + idx)     = __floats2half2_rn(v.x, v.y);
    *reinterpret_cast<__half2*>(g_A2 + idx + 2) = __floats2half2_rn(v.z, v.w);
}

// ---------------------------------------------------------------------------
// GEMM1: U[m, 0..1023] = gamma * (X_f16 . BcatT), fp32 planar out (URe|UIm)
// ---------------------------------------------------------------------------
__global__ __launch_bounds__(256, 2) void gemm1_kernel() {
    extern __shared__ char smem[];
    uint32_t sb = smem_u32(smem);
    const int tid = threadIdx.x;
    const int lane = tid & 31;
    const int warp = tid >> 5;
    const int wm = warp & 3, wn = warp >> 2;
    const int mBase = blockIdx.y * 128;
    const int colBase = blockIdx.x * 128;

    float acc[2][8][4];
#pragma unroll
    for (int a = 0; a < 2; a++)
#pragma unroll
        for (int b = 0; b < 8; b++)
#pragma unroll
            for (int c = 0; c < 4; c++) acc[a][b][c] = 0.f;

    gemm_core(acc,
              g_A2 + (size_t)mBase * K2 + 1024, K2,
              g_Bhi + (size_t)colBase * 256,
              g_Blo + (size_t)colBase * 256, 256,
              8, sb, tid);

    float* dst = (colBase < 512) ? g_URe : g_UIm;
#pragma unroll
    for (int nt = 0; nt < 8; nt++) {
        int col = colBase + wn * 64 + nt * 8 + (lane & 3) * 2;
        int h = col & 511;
        float g0 = g_gamma[h], g1 = g_gamma[h + 1];
#pragma unroll
        for (int mt = 0; mt < 2; mt++) {
            float* c = acc[mt][nt];
            int m0 = mBase + wm * 32 + mt * 16 + (lane >> 2);
            *reinterpret_cast<float2*>(&dst[(size_t)m0 * 512 + h]) =
                make_float2(c[0] * g0, c[1] * g1);
            *reinterpret_cast<float2*>(&dst[(size_t)(m0 + 8) * 512 + h]) =
                make_float2(c[2] * g0, c[3] * g1);
        }
    }
}

// ---------------------------------------------------------------------------
// Scan: chunked-parallel, 16 chunks of 256 (+64 warmup; lambda^64 ~ 1.6e-28).
// Emits ys fp16 into A2 cols [0..1023]; writes h_N planar fp32.
// ---------------------------------------------------------------------------
#define SCH   256
#define SWARM 64
__global__ __launch_bounds__(256) void scan_kernel(float* __restrict__ out_hN) {
    int g = blockIdx.x * blockDim.x + threadIdx.x;
    int h = g & 511;
    int ch = (g >> 9) & 15;
    int b = g >> 13;
    const float2 lam = g_lam[h];
    const float2 cv = g_cvec[h];
    float hr = 0.f, hi = 0.f;
    const int t0 = ch * SCH;
    const int tw = (ch == 0) ? 0 : t0 - SWARM;
    size_t ub = ((size_t)b * TT + tw) * HF + h;
    for (int t = tw; t < t0; t++) {
        float vr = g_URe[ub] + cv.x;
        float vi = g_UIm[ub] + cv.y;
        float nr = fmaf(lam.x, hr, fmaf(-lam.y, hi, vr));
        float ni = fmaf(lam.x, hi, fmaf(lam.y, hr, vi));
        hr = nr; hi = ni; ub += HF;
    }
    size_t arow = ((size_t)b * TT + t0) * K2;
    for (int t = 0; t < SCH; t++) {
        float vr = g_URe[ub] + cv.x;
        float vi = g_UIm[ub] + cv.y;
        float nr = fmaf(lam.x, hr, fmaf(-lam.y, hi, vr));
        float ni = fmaf(lam.x, hi, fmaf(lam.y, hr, vi));
        hr = nr; hi = ni; ub += HF;
        g_A2[arow + h]       = __float2half(hr);
        g_A2[arow + 512 + h] = __float2half(hi);
        arow += K2;
    }
    if (ch == 15) {
        int g2 = b * 512 + h;
        out_hN[g2] = hr;
        out_hN[BATCH * HF + g2] = hi;
    }
}

// ---------------------------------------------------------------------------
// GEMM2: Y[m, 256] = A2 . WcatT + bias   (K = 1280)
// ---------------------------------------------------------------------------
__global__ __launch_bounds__(256, 2) void gemm2_kernel(const float* __restrict__ bias,
                                                       float* __restrict__ Y) {
    extern __shared__ char smem[];
    uint32_t sb = smem_u32(smem);
    const int tid = threadIdx.x;
    const int lane = tid & 31;
    const int warp = tid >> 5;
    const int wm = warp & 3, wn = warp >> 2;
    const int mBase = blockIdx.y * 128;
    const int colBase = blockIdx.x * 128;

    float acc[2][8][4];
#pragma unroll
    for (int a = 0; a < 2; a++)
#pragma unroll
        for (int b = 0; b < 8; b++)
#pragma unroll
            for (int c = 0; c < 4; c++) acc[a][b][c] = 0.f;

    gemm_core(acc,
              g_A2 + (size_t)mBase * K2, K2,
              g_Whi + (size_t)colBase * K2,
              g_Wlo + (size_t)colBase * K2, K2,
              40, sb, tid);

#pragma unroll
    for (int nt = 0; nt < 8; nt++) {
        int col = colBase + wn * 64 + nt * 8 + (lane & 3) * 2;
        float b0 = bias[col], b1 = bias[col + 1];
#pragma unroll
        for (int mt = 0; mt < 2; mt++) {
            float* c = acc[mt][nt];
            int m0 = mBase + wm * 32 + mt * 16 + (lane >> 2);
            *reinterpret_cast<float2*>(&Y[(size_t)m0 * OUTF + col]) =
                make_float2(c[0] + b0, c[1] + b1);
            *reinterpret_cast<float2*>(&Y[(size_t)(m0 + 8) * OUTF + col]) =
                make_float2(c[2] + b0, c[3] + b1);
        }
    }
}

// ---------------------------------------------------------------------------
// Launch
// ---------------------------------------------------------------------------
extern "C" void kernel_launch(void* const* d_in, const int* in_sizes, int n_in,
                              void* d_out, int out_size) {
    const float* X      = (const float*)d_in[0];
    const float* nu_log = (const float*)d_in[1];
    const float* th_log = (const float*)d_in[2];
    const float* Bre    = (const float*)d_in[3];
    const float* Bim    = (const float*)d_in[4];
    const float* Cre    = (const float*)d_in[5];
    const float* Cim    = (const float*)d_in[6];
    const float* D      = (const float*)d_in[7];
    const float* bh_re  = (const float*)d_in[8];
    const float* bh_im  = (const float*)d_in[9];
    const float* bias   = (const float*)d_in[10];

    float* Y = (float*)d_out;
    float* out_hN = Y + Y_ELEMS;

    static int smem_set = 0;
    if (!smem_set) {
        cudaFuncSetAttribute(gemm1_kernel, cudaFuncAttributeMaxDynamicSharedMemorySize, SMEM_BYTES);
        cudaFuncSetAttribute(gemm2_kernel, cudaFuncAttributeMaxDynamicSharedMemorySize, SMEM_BYTES);
        smem_set = 1;
    }

    prep_kernel<<<1, HF>>>(nu_log, th_log, bh_re, bh_im);

    int wtot = 1024 * 256 + 256 * K2;
    wprep_kernel<<<(wtot + 255) / 256, 256>>>(Bre, Bim, Cre, Cim, D);

    convx_kernel<<<(MTOT * INF / 4 + 255) / 256, 256>>>(X);

    dim3 g1(8, MTOT / 128);
    gemm1_kernel<<<g1, 256, SMEM_BYTES>>>();

    scan_kernel<<<(BATCH * 16 * HF) / 256, 256>>>(out_hN);

    dim3 g2(2, MTOT / 128);
    gemm2_kernel<<<g2, 256, SMEM_BYTES>>>(bias, Y);
}

// round 9
// speedup vs baseline: 1.7262x; 1.3601x over previous
#include <cuda_runtime.h>
#include <cuda_fp16.h>
#include <math.h>
#include <stdint.h>

// Problem constants
#define BATCH 16
#define TT    4096
#define INF   256
#define OUTF  256
#define HF    512
#define MTOT  (BATCH * TT)              // 65536
#define K2    1280                      // GEMM2 K = 512 re + 512 im + 256 X
#define Y_ELEMS ((long long)MTOT * OUTF)

// ---------------------------------------------------------------------------
// Scratch (__device__ globals; no allocation APIs)
// ---------------------------------------------------------------------------
__device__ __align__(16) float   g_URe[(size_t)MTOT * HF];
__device__ __align__(16) float   g_UIm[(size_t)MTOT * HF];
__device__ __align__(16) __half  g_A2[(size_t)MTOT * K2];     // fp16 activations
__device__ __align__(16) __half  g_B[1024 * 256];             // fp16 weights (gemm1)
__device__ __align__(16) __half  g_W[256 * K2];               // fp16 weights (gemm2)
__device__ float2 g_lam[HF];
__device__ float2 g_cvec[HF];
__device__ float  g_gamma[HF];

// ---------------------------------------------------------------------------
// PTX helpers (generic PTX only; no sm_103a-only features)
// ---------------------------------------------------------------------------
__device__ __forceinline__ uint32_t smem_u32(const void* p) {
    uint32_t a;
    asm("{ .reg .u64 t; cvta.to.shared.u64 t, %1; cvt.u32.u64 %0, t; }" : "=r"(a) : "l"(p));
    return a;
}
__device__ __forceinline__ void ldsm_x4(uint32_t& r0, uint32_t& r1, uint32_t& r2, uint32_t& r3,
                                        uint32_t addr) {
    asm volatile("ldmatrix.sync.aligned.m8n8.x4.shared.b16 {%0,%1,%2,%3}, [%4];"
                 : "=r"(r0), "=r"(r1), "=r"(r2), "=r"(r3) : "r"(addr));
}
__device__ __forceinline__ void mma16816(float* c, const uint32_t* a, uint32_t b0, uint32_t b1) {
    asm volatile(
        "mma.sync.aligned.m16n8k16.row.col.f32.f16.f16.f32 "
        "{%0,%1,%2,%3}, {%4,%5,%6,%7}, {%8,%9}, {%0,%1,%2,%3};"
        : "+f"(c[0]), "+f"(c[1]), "+f"(c[2]), "+f"(c[3])
        : "r"(a[0]), "r"(a[1]), "r"(a[2]), "r"(a[3]), "r"(b0), "r"(b1));
}
__device__ __forceinline__ void cp_async16(uint32_t sdst, const void* gsrc) {
    asm volatile("cp.async.cg.shared.global [%0], [%1], 16;"
                 :: "r"(sdst), "l"(__cvta_generic_to_global(gsrc)) : "memory");
}
#define CP_COMMIT()  asm volatile("cp.async.commit_group;" ::: "memory")
#define CP_WAIT(n)   asm volatile("cp.async.wait_group %0;" :: "n"(n) : "memory")

// ---------------------------------------------------------------------------
// SMEM: 2 stages x 2 tiles of 128 rows x 32 fp16, row stride 80 B
// ---------------------------------------------------------------------------
#define TSTR   80
#define TILE_B (128 * TSTR)             // 10240
#define S_A    0
#define S_B    (TILE_B)
#define STAGE_B (2 * TILE_B)            // 20480
#define SMEM_BYTES (2 * STAGE_B)        // 40960

__device__ __forceinline__ void ld_tile_async(uint32_t sbase, const __half* __restrict__ g,
                                              int ld, int tid) {
#pragma unroll
    for (int it = 0; it < 2; it++) {
        int u = tid + it * 256;
        int r = u >> 2, j = u & 3;
        cp_async16(sbase + r * TSTR + j * 16, g + (size_t)r * ld + j * 8);
    }
}

__device__ __forceinline__ void ld_stage(uint32_t sb,
                                         const __half* A, int lda,
                                         const __half* B, int ldb,
                                         int kc, int tid) {
    ld_tile_async(sb + S_A, A + kc * 32, lda, tid);
    ld_tile_async(sb + S_B, B + kc * 32, ldb, tid);
}

// Compute one BK=32 chunk: acc += A·B (single-pass fp16).
__device__ __forceinline__ void compute_chunk(float acc[2][8][4], uint32_t sb,
                                              int lane, int wm, int wn) {
    const int a_row = wm * 32 + (lane & 15);
    const uint32_t a_coff = (uint32_t)((lane >> 4) << 4);
    const int b_rowl = (lane & 7) + ((lane >> 4) << 3);
    const uint32_t b_coff = (uint32_t)(((lane >> 3) & 1) << 4);

#pragma unroll
    for (int k16 = 0; k16 < 2; k16++) {
        const uint32_t koff = (uint32_t)(k16 * 32);
        uint32_t ah[2][4], bx[4][4];

        ldsm_x4(ah[0][0], ah[0][1], ah[0][2], ah[0][3],
                sb + S_A + (uint32_t)a_row * TSTR + koff + a_coff);
        ldsm_x4(ah[1][0], ah[1][1], ah[1][2], ah[1][3],
                sb + S_A + (uint32_t)(a_row + 16) * TSTR + koff + a_coff);
#pragma unroll
        for (int ng = 0; ng < 4; ng++)
            ldsm_x4(bx[ng][0], bx[ng][1], bx[ng][2], bx[ng][3],
                    sb + S_B + (uint32_t)(wn * 64 + ng * 16 + b_rowl) * TSTR + koff + b_coff);

#pragma unroll
        for (int ng = 0; ng < 4; ng++) {
            mma16816(acc[0][2 * ng],     ah[0], bx[ng][0], bx[ng][1]);
            mma16816(acc[0][2 * ng + 1], ah[0], bx[ng][2], bx[ng][3]);
            mma16816(acc[1][2 * ng],     ah[1], bx[ng][0], bx[ng][1]);
            mma16816(acc[1][2 * ng + 1], ah[1], bx[ng][2], bx[ng][3]);
        }
    }
}

// Double-buffered GEMM core.
__device__ __forceinline__ void gemm_core(
    float acc[2][8][4],
    const __half* __restrict__ A, int lda,
    const __half* __restrict__ B, int ldb,
    int kChunks, uint32_t sb, int tid) {

    const int lane = tid & 31;
    const int warp = tid >> 5;
    const int wm = warp & 3, wn = warp >> 2;

    ld_stage(sb, A, lda, B, ldb, 0, tid);
    CP_COMMIT();

    for (int kc = 0; kc < kChunks; kc++) {
        if (kc + 1 < kChunks) {
            ld_stage(sb + ((kc + 1) & 1) * STAGE_B, A, lda, B, ldb, kc + 1, tid);
            CP_COMMIT();
            CP_WAIT(1);
        } else {
            CP_WAIT(0);
        }
        __syncthreads();
        compute_chunk(acc, sb + (kc & 1) * STAGE_B, lane, wm, wn);
        __syncthreads();
    }
}

// ---------------------------------------------------------------------------
// Prep kernels
// ---------------------------------------------------------------------------
__global__ void prep_kernel(const float* __restrict__ nu_log,
                            const float* __restrict__ theta_log,
                            const float* __restrict__ bh_re,
                            const float* __restrict__ bh_im) {
    int h = threadIdx.x;
    if (h >= HF) return;
    float en = expf(nu_log[h]);
    float et = expf(theta_log[h]);
    float mag = expf(-en);
    float s, c;
    sincosf(et, &s, &c);
    g_lam[h] = make_float2(mag * c, mag * s);
    float gam = sqrtf(fmaxf(0.0f, 1.0f - mag * mag));
    g_gamma[h] = gam;
    g_cvec[h] = make_float2((gam + 1.0f) * bh_re[h], (gam + 1.0f) * bh_im[h]);
}

// Weights: Bcat = [Bre; Bim] (1024x256), Wcat = [Cre | -Cim | D] (256x1280)
__global__ void wprep_kernel(const float* __restrict__ Bre, const float* __restrict__ Bim,
                             const float* __restrict__ Cre, const float* __restrict__ Cim,
                             const float* __restrict__ D) {
    int n = blockIdx.x * blockDim.x + threadIdx.x;
    if (n < 1024 * 256) {
        int r = n >> 8, i = n & 255;
        float v = (r < 512) ? Bre[r * 256 + i] : Bim[(r - 512) * 256 + i];
        g_B[n] = __float2half(v);
    } else {
        int n2 = n - 1024 * 256;
        if (n2 < 256 * K2) {
            int o = n2 / K2, k = n2 % K2;
            float v;
            if (k < 512)       v = Cre[o * 512 + k];
            else if (k < 1024) v = -Cim[o * 512 + (k - 512)];
            else               v = D[o * 256 + (k - 1024)];
            g_W[n2] = __float2half(v);
        }
    }
}

// X -> fp16 into A2 cols [1024..1279]
__global__ void convx_kernel(const float* __restrict__ X) {
    long long g4 = (long long)blockIdx.x * blockDim.x + threadIdx.x;
    if (g4 >= (long long)MTOT * INF / 4) return;
    int m = (int)(g4 >> 6), i = (int)(g4 & 63) * 4;
    float4 v = *reinterpret_cast<const float4*>(X + (size_t)m * INF + i);
    size_t idx = (size_t)m * K2 + 1024 + i;
    *reinterpret_cast<__half2*>(g_A2 + idx)     = __floats2half2_rn(v.x, v.y);
    *reinterpret_cast<__half2*>(g_A2 + idx + 2) = __floats2half2_rn(v.z, v.w);
}

// ---------------------------------------------------------------------------
// GEMM1: U[m, 0..1023] = gamma * (X_f16 . BcatT), fp32 planar out (URe|UIm)
// ---------------------------------------------------------------------------
__global__ __launch_bounds__(256, 2) void gemm1_kernel() {
    extern __shared__ char smem[];
    uint32_t sb = smem_u32(smem);
    const int tid = threadIdx.x;
    const int lane = tid & 31;
    const int warp = tid >> 5;
    const int wm = warp & 3, wn = warp >> 2;
    const int mBase = blockIdx.y * 128;
    const int colBase = blockIdx.x * 128;

    float acc[2][8][4];
#pragma unroll
    for (int a = 0; a < 2; a++)
#pragma unroll
        for (int b = 0; b < 8; b++)
#pragma unroll
            for (int c = 0; c < 4; c++) acc[a][b][c] = 0.f;

    gemm_core(acc,
              g_A2 + (size_t)mBase * K2 + 1024, K2,
              g_B + (size_t)colBase * 256, 256,
              8, sb, tid);

    float* dst = (colBase < 512) ? g_URe : g_UIm;
#pragma unroll
    for (int nt = 0; nt < 8; nt++) {
        int col = colBase + wn * 64 + nt * 8 + (lane & 3) * 2;
        int h = col & 511;
        float g0 = g_gamma[h], g1 = g_gamma[h + 1];
#pragma unroll
        for (int mt = 0; mt < 2; mt++) {
            float* c = acc[mt][nt];
            int m0 = mBase + wm * 32 + mt * 16 + (lane >> 2);
            *reinterpret_cast<float2*>(&dst[(size_t)m0 * 512 + h]) =
                make_float2(c[0] * g0, c[1] * g1);
            *reinterpret_cast<float2*>(&dst[(size_t)(m0 + 8) * 512 + h]) =
                make_float2(c[2] * g0, c[3] * g1);
        }
    }
}

// ---------------------------------------------------------------------------
// Scan: chunked-parallel, 16 chunks of 256 (+64 warmup; lambda^64 ~ 1.6e-28).
// Emits ys fp16 into A2 cols [0..1023]; writes h_N planar fp32.
// ---------------------------------------------------------------------------
#define SCH   256
#define SWARM 64
__global__ __launch_bounds__(256) void scan_kernel(float* __restrict__ out_hN) {
    int g = blockIdx.x * blockDim.x + threadIdx.x;
    int h = g & 511;
    int ch = (g >> 9) & 15;
    int b = g >> 13;
    const float2 lam = g_lam[h];
    const float2 cv = g_cvec[h];
    float hr = 0.f, hi = 0.f;
    const int t0 = ch * SCH;
    const int tw = (ch == 0) ? 0 : t0 - SWARM;
    size_t ub = ((size_t)b * TT + tw) * HF + h;
    for (int t = tw; t < t0; t++) {
        float vr = g_URe[ub] + cv.x;
        float vi = g_UIm[ub] + cv.y;
        float nr = fmaf(lam.x, hr, fmaf(-lam.y, hi, vr));
        float ni = fmaf(lam.x, hi, fmaf(lam.y, hr, vi));
        hr = nr; hi = ni; ub += HF;
    }
    size_t arow = ((size_t)b * TT + t0) * K2;
    for (int t = 0; t < SCH; t++) {
        float vr = g_URe[ub] + cv.x;
        float vi = g_UIm[ub] + cv.y;
        float nr = fmaf(lam.x, hr, fmaf(-lam.y, hi, vr));
        float ni = fmaf(lam.x, hi, fmaf(lam.y, hr, vi));
        hr = nr; hi = ni; ub += HF;
        g_A2[arow + h]       = __float2half(hr);
        g_A2[arow + 512 + h] = __float2half(hi);
        arow += K2;
    }
    if (ch == 15) {
        int g2 = b * 512 + h;
        out_hN[g2] = hr;
        out_hN[BATCH * HF + g2] = hi;
    }
}

// ---------------------------------------------------------------------------
// GEMM2: Y[m, 256] = A2 . WcatT + bias   (K = 1280)
// ---------------------------------------------------------------------------
__global__ __launch_bounds__(256, 2) void gemm2_kernel(const float* __restrict__ bias,
                                                       float* __restrict__ Y) {
    extern __shared__ char smem[];
    uint32_t sb = smem_u32(smem);
    const int tid = threadIdx.x;
    const int lane = tid & 31;
    const int warp = tid >> 5;
    const int wm = warp & 3, wn = warp >> 2;
    const int mBase = blockIdx.y * 128;
    const int colBase = blockIdx.x * 128;

    float acc[2][8][4];
#pragma unroll
    for (int a = 0; a < 2; a++)
#pragma unroll
        for (int b = 0; b < 8; b++)
#pragma unroll
            for (int c = 0; c < 4; c++) acc[a][b][c] = 0.f;

    gemm_core(acc,
              g_A2 + (size_t)mBase * K2, K2,
              g_W + (size_t)colBase * K2, K2,
              40, sb, tid);

#pragma unroll
    for (int nt = 0; nt < 8; nt++) {
        int col = colBase + wn * 64 + nt * 8 + (lane & 3) * 2;
        float b0 = bias[col], b1 = bias[col + 1];
#pragma unroll
        for (int mt = 0; mt < 2; mt++) {
            float* c = acc[mt][nt];
            int m0 = mBase + wm * 32 + mt * 16 + (lane >> 2);
            *reinterpret_cast<float2*>(&Y[(size_t)m0 * OUTF + col]) =
                make_float2(c[0] + b0, c[1] + b1);
            *reinterpret_cast<float2*>(&Y[(size_t)(m0 + 8) * OUTF + col]) =
                make_float2(c[2] + b0, c[3] + b1);
        }
    }
}

// ---------------------------------------------------------------------------
// Launch
// ---------------------------------------------------------------------------
extern "C" void kernel_launch(void* const* d_in, const int* in_sizes, int n_in,
                              void* d_out, int out_size) {
    const float* X      = (const float*)d_in[0];
    const float* nu_log = (const float*)d_in[1];
    const float* th_log = (const float*)d_in[2];
    const float* Bre    = (const float*)d_in[3];
    const float* Bim    = (const float*)d_in[4];
    const float* Cre    = (const float*)d_in[5];
    const float* Cim    = (const float*)d_in[6];
    const float* D      = (const float*)d_in[7];
    const float* bh_re  = (const float*)d_in[8];
    const float* bh_im  = (const float*)d_in[9];
    const float* bias   = (const float*)d_in[10];

    float* Y = (float*)d_out;
    float* out_hN = Y + Y_ELEMS;

    static int smem_set = 0;
    if (!smem_set) {
        cudaFuncSetAttribute(gemm1_kernel, cudaFuncAttributeMaxDynamicSharedMemorySize, SMEM_BYTES);
        cudaFuncSetAttribute(gemm2_kernel, cudaFuncAttributeMaxDynamicSharedMemorySize, SMEM_BYTES);
        smem_set = 1;
    }

    prep_kernel<<<1, HF>>>(nu_log, th_log, bh_re, bh_im);

    int wtot = 1024 * 256 + 256 * K2;
    wprep_kernel<<<(wtot + 255) / 256, 256>>>(Bre, Bim, Cre, Cim, D);

    convx_kernel<<<(MTOT * INF / 4 + 255) / 256, 256>>>(X);

    dim3 g1(8, MTOT / 128);
    gemm1_kernel<<<g1, 256, SMEM_BYTES>>>();

    scan_kernel<<<(BATCH * 16 * HF) / 256, 256>>>(out_hN);

    dim3 g2(2, MTOT / 128);
    gemm2_kernel<<<g2, 256, SMEM_BYTES>>>(bias, Y);
}

// round 10
// speedup vs baseline: 1.7485x; 1.0130x over previous
#include <cuda_runtime.h>
#include <cuda_fp16.h>
#include <math.h>
#include <stdint.h>

// Problem constants
#define BATCH 16
#define TT    4096
#define INF   256
#define OUTF  256
#define HF    512
#define MTOT  (BATCH * TT)              // 65536
#define K2    1280                      // GEMM2 K = 512 re + 512 im + 256 X
#define Y_ELEMS ((long long)MTOT * OUTF)

// ---------------------------------------------------------------------------
// Scratch (__device__ globals; no allocation APIs)
// ---------------------------------------------------------------------------
__device__ __align__(16) __half  g_URe[(size_t)MTOT * HF];    // fp16 u (re)
__device__ __align__(16) __half  g_UIm[(size_t)MTOT * HF];    // fp16 u (im)
__device__ __align__(16) __half  g_A2[(size_t)MTOT * K2];     // fp16 activations
__device__ __align__(16) __half  g_B[1024 * 256];             // fp16 weights (gemm1)
__device__ __align__(16) __half  g_W[256 * K2];               // fp16 weights (gemm2)
__device__ float2 g_lam[HF];
__device__ float2 g_cvec[HF];
__device__ float  g_gamma[HF];

// ---------------------------------------------------------------------------
// PTX helpers (generic PTX only; no sm_103a-only features)
// ---------------------------------------------------------------------------
__device__ __forceinline__ uint32_t smem_u32(const void* p) {
    uint32_t a;
    asm("{ .reg .u64 t; cvta.to.shared.u64 t, %1; cvt.u32.u64 %0, t; }" : "=r"(a) : "l"(p));
    return a;
}
__device__ __forceinline__ void ldsm_x4(uint32_t& r0, uint32_t& r1, uint32_t& r2, uint32_t& r3,
                                        uint32_t addr) {
    asm volatile("ldmatrix.sync.aligned.m8n8.x4.shared.b16 {%0,%1,%2,%3}, [%4];"
                 : "=r"(r0), "=r"(r1), "=r"(r2), "=r"(r3) : "r"(addr));
}
__device__ __forceinline__ void mma16816(float* c, const uint32_t* a, uint32_t b0, uint32_t b1) {
    asm volatile(
        "mma.sync.aligned.m16n8k16.row.col.f32.f16.f16.f32 "
        "{%0,%1,%2,%3}, {%4,%5,%6,%7}, {%8,%9}, {%0,%1,%2,%3};"
        : "+f"(c[0]), "+f"(c[1]), "+f"(c[2]), "+f"(c[3])
        : "r"(a[0]), "r"(a[1]), "r"(a[2]), "r"(a[3]), "r"(b0), "r"(b1));
}
__device__ __forceinline__ void cp_async16(uint32_t sdst, const void* gsrc) {
    asm volatile("cp.async.cg.shared.global [%0], [%1], 16;"
                 :: "r"(sdst), "l"(__cvta_generic_to_global(gsrc)) : "memory");
}
#define CP_COMMIT()  asm volatile("cp.async.commit_group;" ::: "memory")
#define CP_WAIT(n)   asm volatile("cp.async.wait_group %0;" :: "n"(n) : "memory")

// ---------------------------------------------------------------------------
// SMEM: 2 stages x 2 tiles of 128 rows x 32 fp16, row stride 80 B
// ---------------------------------------------------------------------------
#define TSTR   80
#define TILE_B (128 * TSTR)             // 10240
#define S_A    0
#define S_B    (TILE_B)
#define STAGE_B (2 * TILE_B)            // 20480
#define SMEM_BYTES (2 * STAGE_B)        // 40960

__device__ __forceinline__ void ld_tile_async(uint32_t sbase, const __half* __restrict__ g,
                                              int ld, int tid) {
#pragma unroll
    for (int it = 0; it < 2; it++) {
        int u = tid + it * 256;
        int r = u >> 2, j = u & 3;
        cp_async16(sbase + r * TSTR + j * 16, g + (size_t)r * ld + j * 8);
    }
}

__device__ __forceinline__ void ld_stage(uint32_t sb,
                                         const __half* A, int lda,
                                         const __half* B, int ldb,
                                         int kc, int tid) {
    ld_tile_async(sb + S_A, A + kc * 32, lda, tid);
    ld_tile_async(sb + S_B, B + kc * 32, ldb, tid);
}

// Compute one BK=32 chunk: acc += A·B (single-pass fp16).
__device__ __forceinline__ void compute_chunk(float acc[2][8][4], uint32_t sb,
                                              int lane, int wm, int wn) {
    const int a_row = wm * 32 + (lane & 15);
    const uint32_t a_coff = (uint32_t)((lane >> 4) << 4);
    const int b_rowl = (lane & 7) + ((lane >> 4) << 3);
    const uint32_t b_coff = (uint32_t)(((lane >> 3) & 1) << 4);

#pragma unroll
    for (int k16 = 0; k16 < 2; k16++) {
        const uint32_t koff = (uint32_t)(k16 * 32);
        uint32_t ah[2][4], bx[4][4];

        ldsm_x4(ah[0][0], ah[0][1], ah[0][2], ah[0][3],
                sb + S_A + (uint32_t)a_row * TSTR + koff + a_coff);
        ldsm_x4(ah[1][0], ah[1][1], ah[1][2], ah[1][3],
                sb + S_A + (uint32_t)(a_row + 16) * TSTR + koff + a_coff);
#pragma unroll
        for (int ng = 0; ng < 4; ng++)
            ldsm_x4(bx[ng][0], bx[ng][1], bx[ng][2], bx[ng][3],
                    sb + S_B + (uint32_t)(wn * 64 + ng * 16 + b_rowl) * TSTR + koff + b_coff);

#pragma unroll
        for (int ng = 0; ng < 4; ng++) {
            mma16816(acc[0][2 * ng],     ah[0], bx[ng][0], bx[ng][1]);
            mma16816(acc[0][2 * ng + 1], ah[0], bx[ng][2], bx[ng][3]);
            mma16816(acc[1][2 * ng],     ah[1], bx[ng][0], bx[ng][1]);
            mma16816(acc[1][2 * ng + 1], ah[1], bx[ng][2], bx[ng][3]);
        }
    }
}

// Double-buffered GEMM core.
__device__ __forceinline__ void gemm_core(
    float acc[2][8][4],
    const __half* __restrict__ A, int lda,
    const __half* __restrict__ B, int ldb,
    int kChunks, uint32_t sb, int tid) {

    const int lane = tid & 31;
    const int warp = tid >> 5;
    const int wm = warp & 3, wn = warp >> 2;

    ld_stage(sb, A, lda, B, ldb, 0, tid);
    CP_COMMIT();

    for (int kc = 0; kc < kChunks; kc++) {
        if (kc + 1 < kChunks) {
            ld_stage(sb + ((kc + 1) & 1) * STAGE_B, A, lda, B, ldb, kc + 1, tid);
            CP_COMMIT();
            CP_WAIT(1);
        } else {
            CP_WAIT(0);
        }
        __syncthreads();
        compute_chunk(acc, sb + (kc & 1) * STAGE_B, lane, wm, wn);
        __syncthreads();
    }
}

// ---------------------------------------------------------------------------
// Prep kernels
// ---------------------------------------------------------------------------
__global__ void prep_kernel(const float* __restrict__ nu_log,
                            const float* __restrict__ theta_log,
                            const float* __restrict__ bh_re,
                            const float* __restrict__ bh_im) {
    int h = threadIdx.x;
    if (h >= HF) return;
    float en = expf(nu_log[h]);
    float et = expf(theta_log[h]);
    float mag = expf(-en);
    float s, c;
    sincosf(et, &s, &c);
    g_lam[h] = make_float2(mag * c, mag * s);
    float gam = sqrtf(fmaxf(0.0f, 1.0f - mag * mag));
    g_gamma[h] = gam;
    g_cvec[h] = make_float2((gam + 1.0f) * bh_re[h], (gam + 1.0f) * bh_im[h]);
}

// Weights: Bcat = [Bre; Bim] (1024x256), Wcat = [Cre | -Cim | D] (256x1280)
__global__ void wprep_kernel(const float* __restrict__ Bre, const float* __restrict__ Bim,
                             const float* __restrict__ Cre, const float* __restrict__ Cim,
                             const float* __restrict__ D) {
    int n = blockIdx.x * blockDim.x + threadIdx.x;
    if (n < 1024 * 256) {
        int r = n >> 8, i = n & 255;
        float v = (r < 512) ? Bre[r * 256 + i] : Bim[(r - 512) * 256 + i];
        g_B[n] = __float2half(v);
    } else {
        int n2 = n - 1024 * 256;
        if (n2 < 256 * K2) {
            int o = n2 / K2, k = n2 % K2;
            float v;
            if (k < 512)       v = Cre[o * 512 + k];
            else if (k < 1024) v = -Cim[o * 512 + (k - 512)];
            else               v = D[o * 256 + (k - 1024)];
            g_W[n2] = __float2half(v);
        }
    }
}

// X -> fp16 into A2 cols [1024..1279]
__global__ void convx_kernel(const float* __restrict__ X) {
    long long g4 = (long long)blockIdx.x * blockDim.x + threadIdx.x;
    if (g4 >= (long long)MTOT * INF / 4) return;
    int m = (int)(g4 >> 6), i = (int)(g4 & 63) * 4;
    float4 v = *reinterpret_cast<const float4*>(X + (size_t)m * INF + i);
    size_t idx = (size_t)m * K2 + 1024 + i;
    *reinterpret_cast<__half2*>(g_A2 + idx)     = __floats2half2_rn(v.x, v.y);
    *reinterpret_cast<__half2*>(g_A2 + idx + 2) = __floats2half2_rn(v.z, v.w);
}

// ---------------------------------------------------------------------------
// GEMM1: U[m, 0..1023] = gamma * (X_f16 . BcatT), fp16 planar out (URe|UIm)
// ---------------------------------------------------------------------------
__global__ __launch_bounds__(256, 2) void gemm1_kernel() {
    extern __shared__ char smem[];
    uint32_t sb = smem_u32(smem);
    const int tid = threadIdx.x;
    const int lane = tid & 31;
    const int warp = tid >> 5;
    const int wm = warp & 3, wn = warp >> 2;
    const int mBase = blockIdx.y * 128;
    const int colBase = blockIdx.x * 128;

    float acc[2][8][4];
#pragma unroll
    for (int a = 0; a < 2; a++)
#pragma unroll
        for (int b = 0; b < 8; b++)
#pragma unroll
            for (int c = 0; c < 4; c++) acc[a][b][c] = 0.f;

    gemm_core(acc,
              g_A2 + (size_t)mBase * K2 + 1024, K2,
              g_B + (size_t)colBase * 256, 256,
              8, sb, tid);

    __half* dst = (colBase < 512) ? g_URe : g_UIm;
#pragma unroll
    for (int nt = 0; nt < 8; nt++) {
        int col = colBase + wn * 64 + nt * 8 + (lane & 3) * 2;
        int h = col & 511;
        float g0 = g_gamma[h], g1 = g_gamma[h + 1];
#pragma unroll
        for (int mt = 0; mt < 2; mt++) {
            float* c = acc[mt][nt];
            int m0 = mBase + wm * 32 + mt * 16 + (lane >> 2);
            *reinterpret_cast<__half2*>(&dst[(size_t)m0 * 512 + h]) =
                __floats2half2_rn(c[0] * g0, c[1] * g1);
            *reinterpret_cast<__half2*>(&dst[(size_t)(m0 + 8) * 512 + h]) =
                __floats2half2_rn(c[2] * g0, c[3] * g1);
        }
    }
}

// ---------------------------------------------------------------------------
// Scan: chunked-parallel, 16 chunks of 256 (+64 warmup; lambda^64 ~ 1.6e-28).
// Reads fp16 u, fp32 recurrence in registers, emits ys fp16 into A2;
// writes h_N planar fp32.
// ---------------------------------------------------------------------------
#define SCH   256
#define SWARM 64
__global__ __launch_bounds__(256) void scan_kernel(float* __restrict__ out_hN) {
    int g = blockIdx.x * blockDim.x + threadIdx.x;
    int h = g & 511;
    int ch = (g >> 9) & 15;
    int b = g >> 13;
    const float2 lam = g_lam[h];
    const float2 cv = g_cvec[h];
    float hr = 0.f, hi = 0.f;
    const int t0 = ch * SCH;
    const int tw = (ch == 0) ? 0 : t0 - SWARM;
    size_t ub = ((size_t)b * TT + tw) * HF + h;
    for (int t = tw; t < t0; t++) {
        float vr = __half2float(g_URe[ub]) + cv.x;
        float vi = __half2float(g_UIm[ub]) + cv.y;
        float nr = fmaf(lam.x, hr, fmaf(-lam.y, hi, vr));
        float ni = fmaf(lam.x, hi, fmaf(lam.y, hr, vi));
        hr = nr; hi = ni; ub += HF;
    }
    size_t arow = ((size_t)b * TT + t0) * K2;
    for (int t = 0; t < SCH; t++) {
        float vr = __half2float(g_URe[ub]) + cv.x;
        float vi = __half2float(g_UIm[ub]) + cv.y;
        float nr = fmaf(lam.x, hr, fmaf(-lam.y, hi, vr));
        float ni = fmaf(lam.x, hi, fmaf(lam.y, hr, vi));
        hr = nr; hi = ni; ub += HF;
        g_A2[arow + h]       = __float2half(hr);
        g_A2[arow + 512 + h] = __float2half(hi);
        arow += K2;
    }
    if (ch == 15) {
        int g2 = b * 512 + h;
        out_hN[g2] = hr;
        out_hN[BATCH * HF + g2] = hi;
    }
}

// ---------------------------------------------------------------------------
// GEMM2: Y[m, 256] = A2 . WcatT + bias   (K = 1280)
// ---------------------------------------------------------------------------
__global__ __launch_bounds__(256, 2) void gemm2_kernel(const float* __restrict__ bias,
                                                       float* __restrict__ Y) {
    extern __shared__ char smem[];
    uint32_t sb = smem_u32(smem);
    const int tid = threadIdx.x;
    const int lane = tid & 31;
    const int warp = tid >> 5;
    const int wm = warp & 3, wn = warp >> 2;
    const int mBase = blockIdx.y * 128;
    const int colBase = blockIdx.x * 128;

    float acc[2][8][4];
#pragma unroll
    for (int a = 0; a < 2; a++)
#pragma unroll
        for (int b = 0; b < 8; b++)
#pragma unroll
            for (int c = 0; c < 4; c++) acc[a][b][c] = 0.f;

    gemm_core(acc,
              g_A2 + (size_t)mBase * K2, K2,
              g_W + (size_t)colBase * K2, K2,
              40, sb, tid);

#pragma unroll
    for (int nt = 0; nt < 8; nt++) {
        int col = colBase + wn * 64 + nt * 8 + (lane & 3) * 2;
        float b0 = bias[col], b1 = bias[col + 1];
#pragma unroll
        for (int mt = 0; mt < 2; mt++) {
            float* c = acc[mt][nt];
            int m0 = mBase + wm * 32 + mt * 16 + (lane >> 2);
            *reinterpret_cast<float2*>(&Y[(size_t)m0 * OUTF + col]) =
                make_float2(c[0] + b0, c[1] + b1);
            *reinterpret_cast<float2*>(&Y[(size_t)(m0 + 8) * OUTF + col]) =
                make_float2(c[2] + b0, c[3] + b1);
        }
    }
}

// ---------------------------------------------------------------------------
// Launch
// ---------------------------------------------------------------------------
extern "C" void kernel_launch(void* const* d_in, const int* in_sizes, int n_in,
                              void* d_out, int out_size) {
    const float* X      = (const float*)d_in[0];
    const float* nu_log = (const float*)d_in[1];
    const float* th_log = (const float*)d_in[2];
    const float* Bre    = (const float*)d_in[3];
    const float* Bim    = (const float*)d_in[4];
    const float* Cre    = (const float*)d_in[5];
    const float* Cim    = (const float*)d_in[6];
    const float* D      = (const float*)d_in[7];
    const float* bh_re  = (const float*)d_in[8];
    const float* bh_im  = (const float*)d_in[9];
    const float* bias   = (const float*)d_in[10];

    float* Y = (float*)d_out;
    float* out_hN = Y + Y_ELEMS;

    static int smem_set = 0;
    if (!smem_set) {
        cudaFuncSetAttribute(gemm1_kernel, cudaFuncAttributeMaxDynamicSharedMemorySize, SMEM_BYTES);
        cudaFuncSetAttribute(gemm2_kernel, cudaFuncAttributeMaxDynamicSharedMemorySize, SMEM_BYTES);
        smem_set = 1;
    }

    prep_kernel<<<1, HF>>>(nu_log, th_log, bh_re, bh_im);

    int wtot = 1024 * 256 + 256 * K2;
    wprep_kernel<<<(wtot + 255) / 256, 256>>>(Bre, Bim, Cre, Cim, D);

    convx_kernel<<<(MTOT * INF / 4 + 255) / 256, 256>>>(X);

    dim3 g1(8, MTOT / 128);
    gemm1_kernel<<<g1, 256, SMEM_BYTES>>>();

    scan_kernel<<<(BATCH * 16 * HF) / 256, 256>>>(out_hN);

    dim3 g2(2, MTOT / 128);
    gemm2_kernel<<<g2, 256, SMEM_BYTES>>>(bias, Y);
}

// round 11
// speedup vs baseline: 1.9621x; 1.1221x over previous
#include <cuda_runtime.h>
#include <cuda_fp16.h>
#include <math.h>
#include <stdint.h>

// Problem constants
#define BATCH 16
#define TT    4096
#define INF   256
#define OUTF  256
#define HF    512
#define MTOT  (BATCH * TT)              // 65536
#define K2    1280                      // GEMM2 K = 1024 interleaved ys + 256 X
#define Y_ELEMS ((long long)MTOT * OUTF)

// ---------------------------------------------------------------------------
// Scratch (__device__ globals; no allocation APIs)
// ---------------------------------------------------------------------------
__device__ __align__(16) __half2 g_U2[(size_t)MTOT * HF];     // interleaved (re,im) u
__device__ __align__(16) __half  g_A2[(size_t)MTOT * K2];     // fp16 activations
__device__ __align__(16) __half  g_B[1024 * 256];             // interleaved Bcat rows
__device__ __align__(16) __half  g_W[256 * K2];               // interleaved W cols
__device__ float2 g_lam[HF];
__device__ float2 g_cvec[HF];
__device__ float  g_gamma[HF];

// ---------------------------------------------------------------------------
// PTX helpers (generic PTX only; no sm_103a-only features)
// ---------------------------------------------------------------------------
__device__ __forceinline__ uint32_t smem_u32(const void* p) {
    uint32_t a;
    asm("{ .reg .u64 t; cvta.to.shared.u64 t, %1; cvt.u32.u64 %0, t; }" : "=r"(a) : "l"(p));
    return a;
}
__device__ __forceinline__ void ldsm_x4(uint32_t* r, uint32_t addr) {
    asm volatile("ldmatrix.sync.aligned.m8n8.x4.shared.b16 {%0,%1,%2,%3}, [%4];"
                 : "=r"(r[0]), "=r"(r[1]), "=r"(r[2]), "=r"(r[3]) : "r"(addr));
}
__device__ __forceinline__ void mma16816(float* c, const uint32_t* a, uint32_t b0, uint32_t b1) {
    asm volatile(
        "mma.sync.aligned.m16n8k16.row.col.f32.f16.f16.f32 "
        "{%0,%1,%2,%3}, {%4,%5,%6,%7}, {%8,%9}, {%0,%1,%2,%3};"
        : "+f"(c[0]), "+f"(c[1]), "+f"(c[2]), "+f"(c[3])
        : "r"(a[0]), "r"(a[1]), "r"(a[2]), "r"(a[3]), "r"(b0), "r"(b1));
}
__device__ __forceinline__ void cp_async16(uint32_t sdst, const void* gsrc) {
    asm volatile("cp.async.cg.shared.global [%0], [%1], 16;"
                 :: "r"(sdst), "l"(__cvta_generic_to_global(gsrc)) : "memory");
}
#define CP_COMMIT()  asm volatile("cp.async.commit_group;" ::: "memory")
#define CP_WAIT(n)   asm volatile("cp.async.wait_group %0;" :: "n"(n) : "memory")

// ---------------------------------------------------------------------------
// SMEM: 2 stages x 2 tiles of 128 rows x 32 fp16, row stride 80 B
// ---------------------------------------------------------------------------
#define TSTR   80
#define TILE_B (128 * TSTR)             // 10240
#define S_A    0
#define S_B    (TILE_B)
#define STAGE_B (2 * TILE_B)            // 20480
#define SMEM_BYTES (2 * STAGE_B)        // 40960

// 128 threads: 512 16B units, 4 iters.
__device__ __forceinline__ void ld_tile_async(uint32_t sbase, const __half* __restrict__ g,
                                              int ld, int tid) {
#pragma unroll
    for (int it = 0; it < 4; it++) {
        int u = tid + it * 128;
        int r = u >> 2, j = u & 3;
        cp_async16(sbase + r * TSTR + j * 16, g + (size_t)r * ld + j * 8);
    }
}

__device__ __forceinline__ void ld_stage(uint32_t sb,
                                         const __half* A, int lda,
                                         const __half* B, int ldb,
                                         int kc, int tid) {
    ld_tile_async(sb + S_A, A + kc * 32, lda, tid);
    ld_tile_async(sb + S_B, B + kc * 32, ldb, tid);
}

// Compute one BK=32 chunk with 64x64 warp tiles (4 warps, 2m x 2n grid).
// acc[4 m16-frags][8 n8-frags][4]
__device__ __forceinline__ void compute_chunk(float acc[4][8][4], uint32_t sb,
                                              int lane, int wm, int wn) {
    const uint32_t a_coff = (uint32_t)((lane >> 4) << 4);
    const int a_rl = lane & 15;
    const int b_rowl = (lane & 7) + ((lane >> 4) << 3);
    const uint32_t b_coff = (uint32_t)(((lane >> 3) & 1) << 4);

#pragma unroll
    for (int k16 = 0; k16 < 2; k16++) {
        const uint32_t koff = (uint32_t)(k16 * 32);
        uint32_t ah[4][4], bx[4][4];

#pragma unroll
        for (int mf = 0; mf < 4; mf++)
            ldsm_x4(ah[mf], sb + S_A + (uint32_t)(wm * 64 + mf * 16 + a_rl) * TSTR + koff + a_coff);
#pragma unroll
        for (int ng = 0; ng < 4; ng++)
            ldsm_x4(bx[ng], sb + S_B + (uint32_t)(wn * 64 + ng * 16 + b_rowl) * TSTR + koff + b_coff);

#pragma unroll
        for (int mf = 0; mf < 4; mf++)
#pragma unroll
            for (int ng = 0; ng < 4; ng++) {
                mma16816(acc[mf][2 * ng],     ah[mf], bx[ng][0], bx[ng][1]);
                mma16816(acc[mf][2 * ng + 1], ah[mf], bx[ng][2], bx[ng][3]);
            }
    }
}

// Double-buffered GEMM core (128 threads).
__device__ __forceinline__ void gemm_core(
    float acc[4][8][4],
    const __half* __restrict__ A, int lda,
    const __half* __restrict__ B, int ldb,
    int kChunks, uint32_t sb, int tid) {

    const int lane = tid & 31;
    const int warp = tid >> 5;
    const int wm = warp & 1, wn = warp >> 1;

    ld_stage(sb, A, lda, B, ldb, 0, tid);
    CP_COMMIT();

    for (int kc = 0; kc < kChunks; kc++) {
        if (kc + 1 < kChunks) {
            ld_stage(sb + ((kc + 1) & 1) * STAGE_B, A, lda, B, ldb, kc + 1, tid);
            CP_COMMIT();
            CP_WAIT(1);
        } else {
            CP_WAIT(0);
        }
        __syncthreads();
        compute_chunk(acc, sb + (kc & 1) * STAGE_B, lane, wm, wn);
        __syncthreads();
    }
}

// ---------------------------------------------------------------------------
// Prep kernels
// ---------------------------------------------------------------------------
__global__ void prep_kernel(const float* __restrict__ nu_log,
                            const float* __restrict__ theta_log,
                            const float* __restrict__ bh_re,
                            const float* __restrict__ bh_im) {
    int h = threadIdx.x;
    if (h >= HF) return;
    float en = expf(nu_log[h]);
    float et = expf(theta_log[h]);
    float mag = expf(-en);
    float s, c;
    sincosf(et, &s, &c);
    g_lam[h] = make_float2(mag * c, mag * s);
    float gam = sqrtf(fmaxf(0.0f, 1.0f - mag * mag));
    g_gamma[h] = gam;
    g_cvec[h] = make_float2((gam + 1.0f) * bh_re[h], (gam + 1.0f) * bh_im[h]);
}

// Weights. B rows interleaved: row 2h = Bre[h], row 2h+1 = Bim[h] (1024x256).
// W cols interleaved: col 2h = Cre[o][h], col 2h+1 = -Cim[o][h], cols 1024+ = D.
__global__ void wprep_kernel(const float* __restrict__ Bre, const float* __restrict__ Bim,
                             const float* __restrict__ Cre, const float* __restrict__ Cim,
                             const float* __restrict__ D) {
    int n = blockIdx.x * blockDim.x + threadIdx.x;
    if (n < 1024 * 256) {
        int r = n >> 8, i = n & 255;
        int h = r >> 1;
        float v = (r & 1) ? Bim[h * 256 + i] : Bre[h * 256 + i];
        g_B[n] = __float2half(v);
    } else {
        int n2 = n - 1024 * 256;
        if (n2 < 256 * K2) {
            int o = n2 / K2, k = n2 % K2;
            float v;
            if (k < 1024) {
                int h = k >> 1;
                v = (k & 1) ? -Cim[o * 512 + h] : Cre[o * 512 + h];
            } else {
                v = D[o * 256 + (k - 1024)];
            }
            g_W[n2] = __float2half(v);
        }
    }
}

// X -> fp16 into A2 cols [1024..1279]
__global__ void convx_kernel(const float* __restrict__ X) {
    long long g4 = (long long)blockIdx.x * blockDim.x + threadIdx.x;
    if (g4 >= (long long)MTOT * INF / 4) return;
    int m = (int)(g4 >> 6), i = (int)(g4 & 63) * 4;
    float4 v = *reinterpret_cast<const float4*>(X + (size_t)m * INF + i);
    size_t idx = (size_t)m * K2 + 1024 + i;
    *reinterpret_cast<__half2*>(g_A2 + idx)     = __floats2half2_rn(v.x, v.y);
    *reinterpret_cast<__half2*>(g_A2 + idx + 2) = __floats2half2_rn(v.z, v.w);
}

// ---------------------------------------------------------------------------
// GEMM1: u(re,im) interleaved = gamma * (X_f16 . BcatT). Output: g_U2.
// grid (8, 512), block 128.
// ---------------------------------------------------------------------------
__global__ __launch_bounds__(128, 2) void gemm1_kernel() {
    extern __shared__ char smem[];
    uint32_t sb = smem_u32(smem);
    const int tid = threadIdx.x;
    const int lane = tid & 31;
    const int warp = tid >> 5;
    const int wm = warp & 1, wn = warp >> 1;
    const int mBase = blockIdx.y * 128;
    const int colBase = blockIdx.x * 128;

    float acc[4][8][4];
#pragma unroll
    for (int a = 0; a < 4; a++)
#pragma unroll
        for (int b = 0; b < 8; b++)
#pragma unroll
            for (int c = 0; c < 4; c++) acc[a][b][c] = 0.f;

    gemm_core(acc,
              g_A2 + (size_t)mBase * K2 + 1024, K2,
              g_B + (size_t)colBase * 256, 256,
              8, sb, tid);

    // epilogue: cols are (re,im) pairs; write half2 per element
#pragma unroll
    for (int mf = 0; mf < 4; mf++) {
        int m0 = mBase + wm * 64 + mf * 16 + (lane >> 2);
#pragma unroll
        for (int nf = 0; nf < 8; nf++) {
            int col = colBase + wn * 64 + nf * 8 + (lane & 3) * 2;   // even
            int h = col >> 1;
            float g = g_gamma[h];
            float* c = acc[mf][nf];
            g_U2[(size_t)m0 * HF + h]       = __floats2half2_rn(c[0] * g, c[1] * g);
            g_U2[(size_t)(m0 + 8) * HF + h] = __floats2half2_rn(c[2] * g, c[3] * g);
        }
    }
}

// ---------------------------------------------------------------------------
// Scan: chunked-parallel, 16 chunks of 256 (+32 warmup; lambda^32 ~ 1e-14).
// One half2 load + one half2 store per step. Writes h_N planar fp32.
// ---------------------------------------------------------------------------
#define SCH   256
#define SWARM 32
__global__ __launch_bounds__(256) void scan_kernel(float* __restrict__ out_hN) {
    int g = blockIdx.x * blockDim.x + threadIdx.x;
    int h = g & 511;
    int ch = (g >> 9) & 15;
    int b = g >> 13;
    const float2 lam = g_lam[h];
    const float2 cv = g_cvec[h];
    float hr = 0.f, hi = 0.f;
    const int t0 = ch * SCH;
    const int tw = (ch == 0) ? 0 : t0 - SWARM;
    size_t ub = ((size_t)b * TT + tw) * HF + h;
    for (int t = tw; t < t0; t++) {
        float2 v = __half22float2(g_U2[ub]);
        float vr = v.x + cv.x;
        float vi = v.y + cv.y;
        float nr = fmaf(lam.x, hr, fmaf(-lam.y, hi, vr));
        float ni = fmaf(lam.x, hi, fmaf(lam.y, hr, vi));
        hr = nr; hi = ni; ub += HF;
    }
    size_t arow = ((size_t)b * TT + t0) * K2 + 2 * h;
    for (int t = 0; t < SCH; t++) {
        float2 v = __half22float2(g_U2[ub]);
        float vr = v.x + cv.x;
        float vi = v.y + cv.y;
        float nr = fmaf(lam.x, hr, fmaf(-lam.y, hi, vr));
        float ni = fmaf(lam.x, hi, fmaf(lam.y, hr, vi));
        hr = nr; hi = ni; ub += HF;
        *reinterpret_cast<__half2*>(g_A2 + arow) = __floats2half2_rn(hr, hi);
        arow += K2;
    }
    if (ch == 15) {
        int g2 = b * 512 + h;
        out_hN[g2] = hr;
        out_hN[BATCH * HF + g2] = hi;
    }
}

// ---------------------------------------------------------------------------
// GEMM2: Y[m, 256] = A2 . WcatT + bias   (K = 1280). grid (2, 512), block 128.
// ---------------------------------------------------------------------------
__global__ __launch_bounds__(128, 2) void gemm2_kernel(const float* __restrict__ bias,
                                                       float* __restrict__ Y) {
    extern __shared__ char smem[];
    uint32_t sb = smem_u32(smem);
    const int tid = threadIdx.x;
    const int lane = tid & 31;
    const int warp = tid >> 5;
    const int wm = warp & 1, wn = warp >> 1;
    const int mBase = blockIdx.y * 128;
    const int colBase = blockIdx.x * 128;

    float acc[4][8][4];
#pragma unroll
    for (int a = 0; a < 4; a++)
#pragma unroll
        for (int b = 0; b < 8; b++)
#pragma unroll
            for (int c = 0; c < 4; c++) acc[a][b][c] = 0.f;

    gemm_core(acc,
              g_A2 + (size_t)mBase * K2, K2,
              g_W + (size_t)colBase * K2, K2,
              40, sb, tid);

#pragma unroll
    for (int mf = 0; mf < 4; mf++) {
        int m0 = mBase + wm * 64 + mf * 16 + (lane >> 2);
#pragma unroll
        for (int nf = 0; nf < 8; nf++) {
            int col = colBase + wn * 64 + nf * 8 + (lane & 3) * 2;
            float b0 = bias[col], b1 = bias[col + 1];
            float* c = acc[mf][nf];
            *reinterpret_cast<float2*>(&Y[(size_t)m0 * OUTF + col]) =
                make_float2(c[0] + b0, c[1] + b1);
            *reinterpret_cast<float2*>(&Y[(size_t)(m0 + 8) * OUTF + col]) =
                make_float2(c[2] + b0, c[3] + b1);
        }
    }
}

// ---------------------------------------------------------------------------
// Launch
// ---------------------------------------------------------------------------
extern "C" void kernel_launch(void* const* d_in, const int* in_sizes, int n_in,
                              void* d_out, int out_size) {
    const float* X      = (const float*)d_in[0];
    const float* nu_log = (const float*)d_in[1];
    const float* th_log = (const float*)d_in[2];
    const float* Bre    = (const float*)d_in[3];
    const float* Bim    = (const float*)d_in[4];
    const float* Cre    = (const float*)d_in[5];
    const float* Cim    = (const float*)d_in[6];
    const float* D      = (const float*)d_in[7];
    const float* bh_re  = (const float*)d_in[8];
    const float* bh_im  = (const float*)d_in[9];
    const float* bias   = (const float*)d_in[10];

    float* Y = (float*)d_out;
    float* out_hN = Y + Y_ELEMS;

    static int smem_set = 0;
    if (!smem_set) {
        cudaFuncSetAttribute(gemm1_kernel, cudaFuncAttributeMaxDynamicSharedMemorySize, SMEM_BYTES);
        cudaFuncSetAttribute(gemm2_kernel, cudaFuncAttributeMaxDynamicSharedMemorySize, SMEM_BYTES);
        smem_set = 1;
    }

    prep_kernel<<<1, HF>>>(nu_log, th_log, bh_re, bh_im);

    int wtot = 1024 * 256 + 256 * K2;
    wprep_kernel<<<(wtot + 255) / 256, 256>>>(Bre, Bim, Cre, Cim, D);

    convx_kernel<<<(MTOT * INF / 4 + 255) / 256, 256>>>(X);

    dim3 g1(8, MTOT / 128);
    gemm1_kernel<<<g1, 128, SMEM_BYTES>>>();

    scan_kernel<<<(BATCH * 16 * HF) / 256, 256>>>(out_hN);

    dim3 g2(2, MTOT / 128);
    gemm2_kernel<<<g2, 128, SMEM_BYTES>>>(bias, Y);
}